// round 4
// baseline (speedup 1.0000x reference)
#include <cuda_runtime.h>
#include <cuda_bf16.h>
#include <math.h>

#define T_STEPS 200
#define BATCH   128
#define DIN     784
#define HID     500
#define NOUT    10
#define MROWS   (BATCH * T_STEPS)   // 25600
#define DECAY_M 0.77880078307140487f
#define EPS_BN  1e-5f

// ------------------------- device scratch (no allocs allowed) ---------------
__device__ float g_buf0[MROWS * DIN];   // MLP out / BN+sigmoid / axon1 / gemm1 A
__device__ float g_buf1[MROWS * HID];   // z1 / s1*mask / axon2 out
__device__ float g_buf2[MROWS * HID];   // z2 / s2*mask / axon3 out
__device__ float g_buf3[MROWS * NOUT];  // z3
__device__ float g_m1[MROWS * HID];     // mask1 transposed [B,T,H]
__device__ float g_m2[MROWS * HID];     // mask2 transposed [B,T,H]
__device__ double g_psumd[200 * DIN];   // BN partials (fp64, deterministic)
__device__ float g_mean[DIN];
__device__ float g_rs[DIN];

__device__ __forceinline__ float* bufsel(int s) {
    return s == 0 ? g_buf0 : (s == 1 ? g_buf1 : g_buf2);
}

// Kahan + exact-product accumulate: (s, c) += a*b  (error ~ 2eps per term)
__device__ __forceinline__ void kacc(float a, float b, float& s, float& c) {
    float p = __fmul_rn(a, b);
    float e = __fmaf_rn(a, b, -p);          // exact product low part
    float y = __fsub_rn(p, c);
    float t = __fadd_rn(s, y);
    c = __fsub_rn(__fsub_rn(__fsub_rn(t, s), y), e);
    s = t;
}

// ------------------------- sigmoid: 1/(1+exp(-x)), libdevice expf -----------
__device__ __forceinline__ float sigmoid_exact(float x) {
    return __fdiv_rn(1.0f, __fadd_rn(1.0f, expf(-x)));
}

// ------------------------- mask transpose [B,H,T] -> [B,T,H] ----------------
__global__ void transpose_mask_kernel(const float* __restrict__ in, int msel) {
    float* out = (msel == 1) ? g_m1 : g_m2;
    __shared__ float tile[32][33];
    int b  = blockIdx.x;
    int t0 = blockIdx.y * 32;
    int h0 = blockIdx.z * 32;
#pragma unroll
    for (int i = 0; i < 4; i++) {
        int h = h0 + threadIdx.y + i * 8;
        int t = t0 + threadIdx.x;
        if (h < HID && t < T_STEPS)
            tile[threadIdx.y + i * 8][threadIdx.x] = in[(b * HID + h) * T_STEPS + t];
    }
    __syncthreads();
#pragma unroll
    for (int i = 0; i < 4; i++) {
        int t = t0 + threadIdx.y + i * 8;
        int h = h0 + threadIdx.x;
        if (h < HID && t < T_STEPS)
            out[(b * T_STEPS + t) * HID + h] = tile[threadIdx.x][threadIdx.y + i * 8];
    }
}

// ------------------------- GEMM MLP: near-exact (Kahan) ---------------------
// C[r, n] = sum_i In[b, i, t] * W[n, i],  r = b*T + t.  Block 64x64, thread 4x4.
__global__ void __launch_bounds__(256) gemm_mlp_comp_kernel(
    const float* __restrict__ In, const float* __restrict__ W,
    const float* __restrict__ bias) {
    const int K = DIN, N = DIN;
    __shared__ float As[8][68];
    __shared__ float Bs[8][68];
    int m0 = blockIdx.x * 64, n0 = blockIdx.y * 64;
    int tid = threadIdx.x;
    int tx = tid & 15, ty = tid >> 4;
    float s[4][4], c[4][4];
#pragma unroll
    for (int i = 0; i < 4; i++)
#pragma unroll
        for (int j = 0; j < 4; j++) { s[i][j] = 0.f; c[i][j] = 0.f; }

    for (int k0 = 0; k0 < K; k0 += 8) {
#pragma unroll
        for (int l = 0; l < 2; l++) {
            int e = tid + l * 256;
            int m = e & 63, k = e >> 6;     // consecutive tid -> consecutive m (t)
            int r = m0 + m;
            int bb = r / T_STEPS;
            int t  = r - bb * T_STEPS;
            As[k][m] = In[bb * (DIN * T_STEPS) + (k0 + k) * T_STEPS + t];
        }
#pragma unroll
        for (int l = 0; l < 2; l++) {
            int e = tid + l * 256;
            int n = e >> 3, k = e & 7;
            float v = 0.f;
            if (n0 + n < N) v = W[(n0 + n) * K + (k0 + k)];
            Bs[k][n] = v;
        }
        __syncthreads();
#pragma unroll
        for (int k = 0; k < 8; k++) {
            float a[4], b[4];
#pragma unroll
            for (int i = 0; i < 4; i++) a[i] = As[k][ty * 4 + i];
#pragma unroll
            for (int j = 0; j < 4; j++) b[j] = Bs[k][tx * 4 + j];
#pragma unroll
            for (int i = 0; i < 4; i++)
#pragma unroll
                for (int j = 0; j < 4; j++) kacc(a[i], b[j], s[i][j], c[i][j]);
        }
        __syncthreads();
    }
#pragma unroll
    for (int i = 0; i < 4; i++) {
        int m = m0 + ty * 4 + i;
#pragma unroll
        for (int j = 0; j < 4; j++) {
            int n = n0 + tx * 4 + j;
            if (n < N) {
                float acc = __fsub_rn(s[i][j], c[i][j]);
                g_buf0[m * N + n] = __fadd_rn(acc, bias[n]);
            }
        }
    }
}

// ------------------------- GEMM NT near-exact: C = A*B^T + bias -------------
__global__ void __launch_bounds__(256) gemm_nt_comp_kernel(
    int asel, int csel, const float* __restrict__ B,
    const float* __restrict__ bias, int N, int K) {
    const float* A = bufsel(asel);
    float* C = bufsel(csel);
    __shared__ float As[8][68];
    __shared__ float Bs[8][68];
    int m0 = blockIdx.x * 64, n0 = blockIdx.y * 64;
    int tid = threadIdx.x;
    int tx = tid & 15, ty = tid >> 4;
    float s[4][4], c[4][4];
#pragma unroll
    for (int i = 0; i < 4; i++)
#pragma unroll
        for (int j = 0; j < 4; j++) { s[i][j] = 0.f; c[i][j] = 0.f; }

    for (int k0 = 0; k0 < K; k0 += 8) {
#pragma unroll
        for (int l = 0; l < 2; l++) {
            int e = tid + l * 256;
            int m = e >> 3, k = e & 7;
            float v = 0.f;
            if (k0 + k < K) v = A[(m0 + m) * K + (k0 + k)];
            As[k][m] = v;
        }
#pragma unroll
        for (int l = 0; l < 2; l++) {
            int e = tid + l * 256;
            int n = e >> 3, k = e & 7;
            float v = 0.f;
            if ((n0 + n < N) && (k0 + k < K)) v = B[(n0 + n) * K + (k0 + k)];
            Bs[k][n] = v;
        }
        __syncthreads();
#pragma unroll
        for (int k = 0; k < 8; k++) {
            float a[4], b[4];
#pragma unroll
            for (int i = 0; i < 4; i++) a[i] = As[k][ty * 4 + i];
#pragma unroll
            for (int j = 0; j < 4; j++) b[j] = Bs[k][tx * 4 + j];
#pragma unroll
            for (int i = 0; i < 4; i++)
#pragma unroll
                for (int j = 0; j < 4; j++) kacc(a[i], b[j], s[i][j], c[i][j]);
        }
        __syncthreads();
    }
#pragma unroll
    for (int i = 0; i < 4; i++) {
        int m = m0 + ty * 4 + i;
#pragma unroll
        for (int j = 0; j < 4; j++) {
            int n = n0 + tx * 4 + j;
            if (n < N) {
                float acc = __fsub_rn(s[i][j], c[i][j]);
                C[m * N + n] = __fadd_rn(acc, bias[n]);
            }
        }
    }
}

// ------------------------- BN stats, pass 1: per-channel sum (fp64) ---------
__global__ void bn_stats1_kernel() {
    int blk = blockIdx.x;
    int tid = threadIdx.x;
    double lsum[4] = {0.0, 0.0, 0.0, 0.0};
    int r0 = blk * 128;
    for (int r = r0; r < r0 + 128; r++) {
        const float* row = g_buf0 + r * DIN;
#pragma unroll
        for (int j = 0; j < 4; j++) {
            int c = tid + j * 256;
            if (c < DIN) lsum[j] += (double)row[c];
        }
    }
#pragma unroll
    for (int j = 0; j < 4; j++) {
        int c = tid + j * 256;
        if (c < DIN) g_psumd[blk * DIN + c] = lsum[j];
    }
}

__global__ void bn_fin1_kernel() {
    int c = blockIdx.x * blockDim.x + threadIdx.x;
    if (c >= DIN) return;
    double s = 0.0;
    for (int i = 0; i < 200; i++) s += g_psumd[i * DIN + c];
    float sumf = (float)s;
    g_mean[c] = __fdiv_rn(sumf, (float)MROWS);
}

// ------------------------- BN stats, pass 2: var (fp64 acc of f32 sq dev) ---
__global__ void bn_stats2_kernel() {
    int blk = blockIdx.x;
    int tid = threadIdx.x;
    double lsum[4] = {0.0, 0.0, 0.0, 0.0};
    float mc[4];
#pragma unroll
    for (int j = 0; j < 4; j++) {
        int c = tid + j * 256;
        mc[j] = (c < DIN) ? g_mean[c] : 0.f;
    }
    int r0 = blk * 128;
    for (int r = r0; r < r0 + 128; r++) {
        const float* row = g_buf0 + r * DIN;
#pragma unroll
        for (int j = 0; j < 4; j++) {
            int c = tid + j * 256;
            if (c < DIN) {
                float d = __fsub_rn(row[c], mc[j]);
                float d2 = __fmul_rn(d, d);
                lsum[j] += (double)d2;
            }
        }
    }
#pragma unroll
    for (int j = 0; j < 4; j++) {
        int c = tid + j * 256;
        if (c < DIN) g_psumd[blk * DIN + c] = lsum[j];
    }
}

__global__ void bn_fin2_kernel() {
    int c = blockIdx.x * blockDim.x + threadIdx.x;
    if (c >= DIN) return;
    double s = 0.0;
    for (int i = 0; i < 200; i++) s += g_psumd[i * DIN + c];
    float sumf = (float)s;
    float var = __fdiv_rn(sumf, (float)MROWS);
    g_rs[c] = rsqrtf(__fadd_rn(var, EPS_BN));
}

// ------------------------- BN apply + sigmoid -------------------------------
__global__ void bn_apply_sigmoid_kernel(const float* __restrict__ gamma,
                                        const float* __restrict__ beta) {
    int i = blockIdx.x * blockDim.x + threadIdx.x;
    if (i >= MROWS * DIN) return;
    int c = i % DIN;
    float t = __fsub_rn(g_buf0[i], g_mean[c]);
    t = __fmul_rn(gamma[c], t);
    t = __fmul_rn(t, g_rs[c]);
    t = __fadd_rn(t, beta[c]);
    g_buf0[i] = sigmoid_exact(t);
}

// ------------------------- axon: second-order IIR over T (in place) ---------
__global__ void axon_kernel(int bsel, const float* __restrict__ a1,
                            const float* __restrict__ a2, int C) {
    float* buf = bufsel(bsel);
    int idx = blockIdx.x * blockDim.x + threadIdx.x;
    if (idx >= BATCH * C) return;
    int b = idx / C, c = idx - b * C;
    float A1 = a1[c], A2 = a2[c];
    float p1 = 0.f, p2 = 0.f;
    int off = b * T_STEPS * C + c;
    for (int t = 0; t < T_STEPS; t++, off += C) {
        float x = buf[off];
        float p = __fadd_rn(__fadd_rn(__fmul_rn(A1, p1), __fmul_rn(A2, p2)), x);
        buf[off] = p;
        p2 = p1;
        p1 = p;
    }
}

// ------------------------- LIF scan + dropout mask (in place) ---------------
__global__ void lif_kernel(int bsel, int msel) {
    float* buf = bufsel(bsel);
    const float* mask = (msel == 1) ? g_m1 : g_m2;
    int idx = blockIdx.x * blockDim.x + threadIdx.x;
    if (idx >= BATCH * HID) return;
    int b = idx / HID, c = idx - b * HID;
    float v = 0.f, s = 0.f;
    int off = b * T_STEPS * HID + c;
    for (int t = 0; t < T_STEPS; t++, off += HID) {
        float z = buf[off];
        v = __fadd_rn(__fmul_rn(__fmul_rn(DECAY_M, v), __fsub_rn(1.0f, s)), z);
        s = (v > 1.0f) ? 1.0f : 0.0f;
        buf[off] = __fmul_rn(s, mask[off]);
    }
}

// ------------------------- GEMM3 (N=10): Kahan near-exact --------------------
__global__ void __launch_bounds__(256) gemm3_kernel(
    const float* __restrict__ W3, const float* __restrict__ b3) {
    __shared__ float sW[NOUT][HID];
    int tid = threadIdx.x;
    for (int i = tid; i < NOUT * HID; i += 256) sW[i / HID][i % HID] = W3[i];
    __syncthreads();
    int idx = blockIdx.x * 256 + tid;
    int r = idx / NOUT, o = idx - r * NOUT;
    const float* a = g_buf2 + r * HID;
    float s = 0.f, c = 0.f;
    for (int k = 0; k < HID; k++) kacc(a[k], sW[o][k], s, c);
    float acc = __fsub_rn(s, c);
    g_buf3[r * NOUT + o] = __fadd_rn(acc, b3[o]);
}

// ------------------------- final LIF + output transpose [B,10,T] ------------
__global__ void lif3_out_kernel(float* __restrict__ out) {
    int idx = blockIdx.x * blockDim.x + threadIdx.x;
    if (idx >= BATCH * NOUT) return;
    int b = idx / NOUT, o = idx - b * NOUT;
    float v = 0.f, s = 0.f;
    for (int t = 0; t < T_STEPS; t++) {
        float z = g_buf3[(b * T_STEPS + t) * NOUT + o];
        v = __fadd_rn(__fmul_rn(__fmul_rn(DECAY_M, v), __fsub_rn(1.0f, s)), z);
        s = (v > 1.0f) ? 1.0f : 0.0f;
        out[(b * NOUT + o) * T_STEPS + t] = s;
    }
}

// ------------------------- launch -------------------------------------------
extern "C" void kernel_launch(void* const* d_in, const int* in_sizes, int n_in,
                              void* d_out, int out_size) {
    const float* inputs = (const float*)d_in[0];
    const float* W_mlp  = (const float*)d_in[1];
    const float* b_mlp  = (const float*)d_in[2];
    const float* gamma  = (const float*)d_in[3];
    const float* beta   = (const float*)d_in[4];
    const float* a1_1   = (const float*)d_in[5];
    const float* a2_1   = (const float*)d_in[6];
    const float* W1     = (const float*)d_in[7];
    const float* b1     = (const float*)d_in[8];
    const float* a1_2   = (const float*)d_in[9];
    const float* a2_2   = (const float*)d_in[10];
    const float* W2     = (const float*)d_in[11];
    const float* b2     = (const float*)d_in[12];
    const float* a1_3   = (const float*)d_in[13];
    const float* a2_3   = (const float*)d_in[14];
    const float* W3     = (const float*)d_in[15];
    const float* b3     = (const float*)d_in[16];
    const float* mask1  = (const float*)d_in[17];
    const float* mask2  = (const float*)d_in[18];
    float* out = (float*)d_out;

    transpose_mask_kernel<<<dim3(BATCH, 7, 16), dim3(32, 8)>>>(mask1, 1);
    transpose_mask_kernel<<<dim3(BATCH, 7, 16), dim3(32, 8)>>>(mask2, 2);

    gemm_mlp_comp_kernel<<<dim3(MROWS / 64, (DIN + 63) / 64), 256>>>(inputs, W_mlp, b_mlp);

    bn_stats1_kernel<<<200, 256>>>();
    bn_fin1_kernel<<<(DIN + 255) / 256, 256>>>();
    bn_stats2_kernel<<<200, 256>>>();
    bn_fin2_kernel<<<(DIN + 255) / 256, 256>>>();
    bn_apply_sigmoid_kernel<<<(MROWS * DIN + 255) / 256, 256>>>(gamma, beta);

    axon_kernel<<<(BATCH * DIN + 255) / 256, 256>>>(0, a1_1, a2_1, DIN);
    gemm_nt_comp_kernel<<<dim3(MROWS / 64, (HID + 63) / 64), 256>>>(0, 1, W1, b1, HID, DIN);
    lif_kernel<<<(BATCH * HID + 255) / 256, 256>>>(1, 1);

    axon_kernel<<<(BATCH * HID + 255) / 256, 256>>>(1, a1_2, a2_2, HID);
    gemm_nt_comp_kernel<<<dim3(MROWS / 64, (HID + 63) / 64), 256>>>(1, 2, W2, b2, HID, HID);
    lif_kernel<<<(BATCH * HID + 255) / 256, 256>>>(2, 2);

    axon_kernel<<<(BATCH * HID + 255) / 256, 256>>>(2, a1_3, a2_3, HID);
    gemm3_kernel<<<MROWS * NOUT / 256, 256>>>(W3, b3);
    lif3_out_kernel<<<(BATCH * NOUT + 255) / 256, 256>>>(out);
}

// round 5
// speedup vs baseline: 1.5818x; 1.5818x over previous
#include <cuda_runtime.h>
#include <cuda_bf16.h>
#include <math.h>

#define T_STEPS 200
#define BATCH   128
#define DIN     784
#define HID     500
#define NOUT    10
#define MROWS   (BATCH * T_STEPS)   // 25600
#define DECAY_M 0.77880078307140487f
#define EPS_BN  1e-5f
#define NSTATB  800                  // BN stats blocks (32 rows each)

// ------------------------- device scratch (no allocs allowed) ---------------
__device__ float g_buf0[MROWS * DIN];   // MLP out -> (BN+sig+axon1 in place)
__device__ float g_buf1[MROWS * HID];   // z1 / s1*mask / axon2 out
__device__ float g_buf2[MROWS * HID];   // z2 / s2*mask / axon3 out
__device__ float g_buf3[MROWS * NOUT];  // z3
__device__ double g_psumd[NSTATB * DIN];
__device__ double g_psqd [NSTATB * DIN];
__device__ float g_mean[DIN];
__device__ float g_rs[DIN];

__device__ __forceinline__ float* bufsel(int s) {
    return s == 0 ? g_buf0 : (s == 1 ? g_buf1 : g_buf2);
}

// 4-op compensated accumulate: (s,c) += a*b
// y = fl(ab - c) single rounding; add error captured in c.
// Worst-case error ~ eps * sum|a*b|  (same class as classic Kahan).
__device__ __forceinline__ void kacc2(float a, float b, float& s, float& c) {
    float y = __fmaf_rn(a, b, -c);
    float t = __fadd_rn(s, y);
    c = __fsub_rn(__fsub_rn(t, s), y);
    s = t;
}

__device__ __forceinline__ float sigmoid_exact(float x) {
    return __fdiv_rn(1.0f, __fadd_rn(1.0f, expf(-x)));
}

// ------------------------- GEMM MLP: compensated ----------------------------
// C[r, n] = sum_i In[b, i, t] * W[n, i],  r = b*T + t.  Block 64x64, thread 4x4.
__global__ void __launch_bounds__(256) gemm_mlp_comp_kernel(
    const float* __restrict__ In, const float* __restrict__ W,
    const float* __restrict__ bias) {
    const int K = DIN, N = DIN;
    __shared__ float As[8][68];
    __shared__ float Bs[8][68];
    int m0 = blockIdx.x * 64, n0 = blockIdx.y * 64;
    int tid = threadIdx.x;
    int tx = tid & 15, ty = tid >> 4;
    float s[4][4], c[4][4];
#pragma unroll
    for (int i = 0; i < 4; i++)
#pragma unroll
        for (int j = 0; j < 4; j++) { s[i][j] = 0.f; c[i][j] = 0.f; }

    for (int k0 = 0; k0 < K; k0 += 8) {
#pragma unroll
        for (int l = 0; l < 2; l++) {
            int e = tid + l * 256;
            int m = e & 63, k = e >> 6;
            int r = m0 + m;
            int bb = r / T_STEPS;
            int t  = r - bb * T_STEPS;
            As[k][m] = In[bb * (DIN * T_STEPS) + (k0 + k) * T_STEPS + t];
        }
#pragma unroll
        for (int l = 0; l < 2; l++) {
            int e = tid + l * 256;
            int n = e >> 3, k = e & 7;
            float v = 0.f;
            if (n0 + n < N) v = W[(n0 + n) * K + (k0 + k)];
            Bs[k][n] = v;
        }
        __syncthreads();
#pragma unroll
        for (int k = 0; k < 8; k++) {
            float a[4], b[4];
#pragma unroll
            for (int i = 0; i < 4; i++) a[i] = As[k][ty * 4 + i];
#pragma unroll
            for (int j = 0; j < 4; j++) b[j] = Bs[k][tx * 4 + j];
#pragma unroll
            for (int i = 0; i < 4; i++)
#pragma unroll
                for (int j = 0; j < 4; j++) kacc2(a[i], b[j], s[i][j], c[i][j]);
        }
        __syncthreads();
    }
#pragma unroll
    for (int i = 0; i < 4; i++) {
        int m = m0 + ty * 4 + i;
#pragma unroll
        for (int j = 0; j < 4; j++) {
            int n = n0 + tx * 4 + j;
            if (n < N) {
                float acc = __fsub_rn(s[i][j], c[i][j]);
                g_buf0[m * N + n] = __fadd_rn(acc, bias[n]);
            }
        }
    }
}

// ------------------------- GEMM NT compensated: C = A*B^T + bias ------------
__global__ void __launch_bounds__(256) gemm_nt_comp_kernel(
    int asel, int csel, const float* __restrict__ B,
    const float* __restrict__ bias, int N, int K) {
    const float* A = bufsel(asel);
    float* C = bufsel(csel);
    __shared__ float As[8][68];
    __shared__ float Bs[8][68];
    int m0 = blockIdx.x * 64, n0 = blockIdx.y * 64;
    int tid = threadIdx.x;
    int tx = tid & 15, ty = tid >> 4;
    float s[4][4], c[4][4];
#pragma unroll
    for (int i = 0; i < 4; i++)
#pragma unroll
        for (int j = 0; j < 4; j++) { s[i][j] = 0.f; c[i][j] = 0.f; }

    for (int k0 = 0; k0 < K; k0 += 8) {
#pragma unroll
        for (int l = 0; l < 2; l++) {
            int e = tid + l * 256;
            int m = e >> 3, k = e & 7;
            float v = 0.f;
            if (k0 + k < K) v = A[(m0 + m) * K + (k0 + k)];
            As[k][m] = v;
        }
#pragma unroll
        for (int l = 0; l < 2; l++) {
            int e = tid + l * 256;
            int n = e >> 3, k = e & 7;
            float v = 0.f;
            if ((n0 + n < N) && (k0 + k < K)) v = B[(n0 + n) * K + (k0 + k)];
            Bs[k][n] = v;
        }
        __syncthreads();
#pragma unroll
        for (int k = 0; k < 8; k++) {
            float a[4], b[4];
#pragma unroll
            for (int i = 0; i < 4; i++) a[i] = As[k][ty * 4 + i];
#pragma unroll
            for (int j = 0; j < 4; j++) b[j] = Bs[k][tx * 4 + j];
#pragma unroll
            for (int i = 0; i < 4; i++)
#pragma unroll
                for (int j = 0; j < 4; j++) kacc2(a[i], b[j], s[i][j], c[i][j]);
        }
        __syncthreads();
    }
#pragma unroll
    for (int i = 0; i < 4; i++) {
        int m = m0 + ty * 4 + i;
#pragma unroll
        for (int j = 0; j < 4; j++) {
            int n = n0 + tx * 4 + j;
            if (n < N) {
                float acc = __fsub_rn(s[i][j], c[i][j]);
                C[m * N + n] = __fadd_rn(acc, bias[n]);
            }
        }
    }
}

// ------------------------- BN stats: single pass fp64 sum + sumsq -----------
__global__ void bn_stats_kernel() {
    int blk = blockIdx.x;
    int tid = threadIdx.x;
    double ls[4] = {0.0, 0.0, 0.0, 0.0};
    double lq[4] = {0.0, 0.0, 0.0, 0.0};
    int r0 = blk * (MROWS / NSTATB);
    for (int r = r0; r < r0 + (MROWS / NSTATB); r++) {
        const float* row = g_buf0 + r * DIN;
#pragma unroll
        for (int j = 0; j < 4; j++) {
            int c = tid + j * 256;
            if (c < DIN) {
                double v = (double)row[c];
                ls[j] += v;
                lq[j] += v * v;
            }
        }
    }
#pragma unroll
    for (int j = 0; j < 4; j++) {
        int c = tid + j * 256;
        if (c < DIN) {
            g_psumd[blk * DIN + c] = ls[j];
            g_psqd [blk * DIN + c] = lq[j];
        }
    }
}

__global__ void bn_fin_kernel() {
    int c = blockIdx.x * blockDim.x + threadIdx.x;
    if (c >= DIN) return;
    double s = 0.0, q = 0.0;
    for (int i = 0; i < NSTATB; i++) {
        s += g_psumd[i * DIN + c];
        q += g_psqd [i * DIN + c];
    }
    float sumf = (float)s;
    g_mean[c] = __fdiv_rn(sumf, (float)MROWS);
    double meand = s / (double)MROWS;
    double vard = q / (double)MROWS - meand * meand;
    float var = (float)vard;
    g_rs[c] = rsqrtf(__fadd_rn(var, EPS_BN));
}

// ------------------------- fused BN apply + sigmoid + axon1 (in place) ------
__global__ void axon1_bn_kernel(const float* __restrict__ gamma,
                                const float* __restrict__ beta,
                                const float* __restrict__ a1,
                                const float* __restrict__ a2) {
    int idx = blockIdx.x * blockDim.x + threadIdx.x;
    if (idx >= BATCH * DIN) return;
    int b = idx / DIN, c = idx - b * DIN;
    float A1 = a1[c], A2 = a2[c];
    float mean = g_mean[c], rs = g_rs[c], gm = gamma[c], bt = beta[c];
    float p1 = 0.f, p2 = 0.f;
    int off = b * T_STEPS * DIN + c;
    for (int t = 0; t < T_STEPS; t++, off += DIN) {
        float v = __fsub_rn(g_buf0[off], mean);
        v = __fmul_rn(gm, v);
        v = __fmul_rn(v, rs);
        v = __fadd_rn(v, bt);
        float x = sigmoid_exact(v);
        float p = __fadd_rn(__fadd_rn(__fmul_rn(A1, p1), __fmul_rn(A2, p2)), x);
        g_buf0[off] = p;
        p2 = p1;
        p1 = p;
    }
}

// ------------------------- axon (layers 2,3): IIR over T (in place) ---------
__global__ void axon_kernel(int bsel, const float* __restrict__ a1,
                            const float* __restrict__ a2, int C) {
    float* buf = bufsel(bsel);
    int idx = blockIdx.x * blockDim.x + threadIdx.x;
    if (idx >= BATCH * C) return;
    int b = idx / C, c = idx - b * C;
    float A1 = a1[c], A2 = a2[c];
    float p1 = 0.f, p2 = 0.f;
    int off = b * T_STEPS * C + c;
    for (int t = 0; t < T_STEPS; t++, off += C) {
        float x = buf[off];
        float p = __fadd_rn(__fadd_rn(__fmul_rn(A1, p1), __fmul_rn(A2, p2)), x);
        buf[off] = p;
        p2 = p1;
        p1 = p;
    }
}

// ------------------------- LIF scan + dropout mask (mask read [B,H,T]) ------
__global__ void lif_kernel(int bsel, const float* __restrict__ mask) {
    float* buf = bufsel(bsel);
    int idx = blockIdx.x * blockDim.x + threadIdx.x;
    if (idx >= BATCH * HID) return;
    int b = idx / HID, c = idx - b * HID;
    float v = 0.f, s = 0.f;
    int off = b * T_STEPS * HID + c;
    int moff = (b * HID + c) * T_STEPS;
    for (int t = 0; t < T_STEPS; t++, off += HID) {
        float z = buf[off];
        v = __fadd_rn(__fmul_rn(__fmul_rn(DECAY_M, v), __fsub_rn(1.0f, s)), z);
        s = (v > 1.0f) ? 1.0f : 0.0f;
        buf[off] = __fmul_rn(s, mask[moff + t]);
    }
}

// ------------------------- GEMM3 (N=10): compensated ------------------------
__global__ void __launch_bounds__(256) gemm3_kernel(
    const float* __restrict__ W3, const float* __restrict__ b3) {
    __shared__ float sW[NOUT][HID];
    int tid = threadIdx.x;
    for (int i = tid; i < NOUT * HID; i += 256) sW[i / HID][i % HID] = W3[i];
    __syncthreads();
    int idx = blockIdx.x * 256 + tid;
    int r = idx / NOUT, o = idx - r * NOUT;
    const float* a = g_buf2 + r * HID;
    float s = 0.f, c = 0.f;
    for (int k = 0; k < HID; k++) kacc2(a[k], sW[o][k], s, c);
    float acc = __fsub_rn(s, c);
    g_buf3[r * NOUT + o] = __fadd_rn(acc, b3[o]);
}

// ------------------------- final LIF + output transpose [B,10,T] ------------
__global__ void lif3_out_kernel(float* __restrict__ out) {
    int idx = blockIdx.x * blockDim.x + threadIdx.x;
    if (idx >= BATCH * NOUT) return;
    int b = idx / NOUT, o = idx - b * NOUT;
    float v = 0.f, s = 0.f;
    for (int t = 0; t < T_STEPS; t++) {
        float z = g_buf3[(b * T_STEPS + t) * NOUT + o];
        v = __fadd_rn(__fmul_rn(__fmul_rn(DECAY_M, v), __fsub_rn(1.0f, s)), z);
        s = (v > 1.0f) ? 1.0f : 0.0f;
        out[(b * NOUT + o) * T_STEPS + t] = s;
    }
}

// ------------------------- launch -------------------------------------------
extern "C" void kernel_launch(void* const* d_in, const int* in_sizes, int n_in,
                              void* d_out, int out_size) {
    const float* inputs = (const float*)d_in[0];
    const float* W_mlp  = (const float*)d_in[1];
    const float* b_mlp  = (const float*)d_in[2];
    const float* gamma  = (const float*)d_in[3];
    const float* beta   = (const float*)d_in[4];
    const float* a1_1   = (const float*)d_in[5];
    const float* a2_1   = (const float*)d_in[6];
    const float* W1     = (const float*)d_in[7];
    const float* b1     = (const float*)d_in[8];
    const float* a1_2   = (const float*)d_in[9];
    const float* a2_2   = (const float*)d_in[10];
    const float* W2     = (const float*)d_in[11];
    const float* b2     = (const float*)d_in[12];
    const float* a1_3   = (const float*)d_in[13];
    const float* a2_3   = (const float*)d_in[14];
    const float* W3     = (const float*)d_in[15];
    const float* b3     = (const float*)d_in[16];
    const float* mask1  = (const float*)d_in[17];
    const float* mask2  = (const float*)d_in[18];
    float* out = (float*)d_out;

    gemm_mlp_comp_kernel<<<dim3(MROWS / 64, (DIN + 63) / 64), 256>>>(inputs, W_mlp, b_mlp);

    bn_stats_kernel<<<NSTATB, 256>>>();
    bn_fin_kernel<<<(DIN + 255) / 256, 256>>>();

    axon1_bn_kernel<<<(BATCH * DIN + 255) / 256, 256>>>(gamma, beta, a1_1, a2_1);
    gemm_nt_comp_kernel<<<dim3(MROWS / 64, (HID + 63) / 64), 256>>>(0, 1, W1, b1, HID, DIN);
    lif_kernel<<<(BATCH * HID + 255) / 256, 256>>>(1, mask1);

    axon_kernel<<<(BATCH * HID + 255) / 256, 256>>>(1, a1_2, a2_2, HID);
    gemm_nt_comp_kernel<<<dim3(MROWS / 64, (HID + 63) / 64), 256>>>(1, 2, W2, b2, HID, HID);
    lif_kernel<<<(BATCH * HID + 255) / 256, 256>>>(2, mask2);

    axon_kernel<<<(BATCH * HID + 255) / 256, 256>>>(2, a1_3, a2_3, HID);
    gemm3_kernel<<<MROWS * NOUT / 256, 256>>>(W3, b3);
    lif3_out_kernel<<<(BATCH * NOUT + 255) / 256, 256>>>(out);
}

// round 6
// speedup vs baseline: 1.7308x; 1.0942x over previous
#include <cuda_runtime.h>
#include <cuda_bf16.h>
#include <math.h>

#define T_STEPS 200
#define BATCH   128
#define DIN     784
#define HID     500
#define NOUT    10
#define MROWS   (BATCH * T_STEPS)   // 25600
#define DECAY_M 0.77880078307140487f
#define EPS_BN  1e-5f
#define NSTATB  800

typedef unsigned long long ull;

// ------------------------- device scratch (no allocs allowed) ---------------
__device__ float g_buf0[MROWS * DIN];
__device__ float g_buf1[MROWS * HID];
__device__ float g_buf2[MROWS * HID];
__device__ float g_buf3[MROWS * NOUT];
__device__ double g_psumd[NSTATB * DIN];
__device__ double g_psqd [NSTATB * DIN];
__device__ float g_mean[DIN];
__device__ float g_rs[DIN];

__device__ __forceinline__ float* bufsel(int s) {
    return s == 0 ? g_buf0 : (s == 1 ? g_buf1 : g_buf2);
}

// ------------------------- packed f32x2 helpers -----------------------------
__device__ __forceinline__ ull pack2(float lo, float hi) {
    ull r;
    asm("mov.b64 %0, {%1, %2};" : "=l"(r) : "f"(lo), "f"(hi));
    return r;
}
__device__ __forceinline__ void unpack2(ull v, float& lo, float& hi) {
    asm("mov.b64 {%0, %1}, %2;" : "=f"(lo), "=f"(hi) : "l"(v));
}

// Packed compensated accumulate, 2 lanes:  per lane (s,c) += a*b with
// cneg == -c tracked:  y = fl(ab + cneg) = fl(ab - c);  t = s + y;
// cneg' = y - (t - s) = -((t-s) - y);  s = t.
// Lane-wise IEEE rn — bitwise identical to the scalar kacc2 of round 5.
__device__ __forceinline__ void kacc2x2(ull a, ull b, ull& s, ull& cneg) {
    ull y, t, d;
    asm("fma.rn.f32x2 %0, %1, %2, %3;" : "=l"(y) : "l"(a), "l"(b), "l"(cneg));
    asm("add.rn.f32x2 %0, %1, %2;" : "=l"(t) : "l"(s), "l"(y));
    asm("sub.rn.f32x2 %0, %1, %2;" : "=l"(d) : "l"(t), "l"(s));
    asm("sub.rn.f32x2 %0, %1, %2;" : "=l"(cneg) : "l"(y), "l"(d));
    s = t;
}

// scalar version (gemm3)
__device__ __forceinline__ void kacc2(float a, float b, float& s, float& c) {
    float y = __fmaf_rn(a, b, -c);
    float t = __fadd_rn(s, y);
    c = __fsub_rn(__fsub_rn(t, s), y);
    s = t;
}

__device__ __forceinline__ float sigmoid_exact(float x) {
    return __fdiv_rn(1.0f, __fadd_rn(1.0f, expf(-x)));
}

// ------------------------- GEMM MLP: packed compensated ---------------------
// C[r, n] = sum_i In[b, i, t] * W[n, i],  r = b*T + t.  Block 64x64, thread 4x4.
__global__ void __launch_bounds__(256) gemm_mlp_comp_kernel(
    const float* __restrict__ In, const float* __restrict__ W,
    const float* __restrict__ bias) {
    const int K = DIN, N = DIN;
    __shared__ __align__(16) float As[8][68];
    __shared__ __align__(16) float Bs[8][68];
    int m0 = blockIdx.x * 64, n0 = blockIdx.y * 64;
    int tid = threadIdx.x;
    int tx = tid & 15, ty = tid >> 4;
    ull s2[4][2], c2[4][2];
#pragma unroll
    for (int i = 0; i < 4; i++)
#pragma unroll
        for (int j = 0; j < 2; j++) { s2[i][j] = 0ull; c2[i][j] = 0ull; }

    for (int k0 = 0; k0 < K; k0 += 8) {
#pragma unroll
        for (int l = 0; l < 2; l++) {
            int e = tid + l * 256;
            int m = e & 63, k = e >> 6;
            int r = m0 + m;
            int bb = r / T_STEPS;
            int t  = r - bb * T_STEPS;
            As[k][m] = In[bb * (DIN * T_STEPS) + (k0 + k) * T_STEPS + t];
        }
#pragma unroll
        for (int l = 0; l < 2; l++) {
            int e = tid + l * 256;
            int n = e >> 3, k = e & 7;
            float v = 0.f;
            if (n0 + n < N) v = W[(n0 + n) * K + (k0 + k)];
            Bs[k][n] = v;
        }
        __syncthreads();
#pragma unroll
        for (int k = 0; k < 8; k++) {
            float4 av = *reinterpret_cast<const float4*>(&As[k][ty * 4]);
            const ull* pb = reinterpret_cast<const ull*>(&Bs[k][tx * 4]);
            ull b0 = pb[0], b1 = pb[1];
            ull a0 = pack2(av.x, av.x);
            ull a1 = pack2(av.y, av.y);
            ull a2 = pack2(av.z, av.z);
            ull a3 = pack2(av.w, av.w);
            kacc2x2(a0, b0, s2[0][0], c2[0][0]);
            kacc2x2(a0, b1, s2[0][1], c2[0][1]);
            kacc2x2(a1, b0, s2[1][0], c2[1][0]);
            kacc2x2(a1, b1, s2[1][1], c2[1][1]);
            kacc2x2(a2, b0, s2[2][0], c2[2][0]);
            kacc2x2(a2, b1, s2[2][1], c2[2][1]);
            kacc2x2(a3, b0, s2[3][0], c2[3][0]);
            kacc2x2(a3, b1, s2[3][1], c2[3][1]);
        }
        __syncthreads();
    }
#pragma unroll
    for (int i = 0; i < 4; i++) {
        int m = m0 + ty * 4 + i;
#pragma unroll
        for (int jj = 0; jj < 2; jj++) {
            float slo, shi, clo, chi;
            unpack2(s2[i][jj], slo, shi);
            unpack2(c2[i][jj], clo, chi);
            int n = n0 + tx * 4 + 2 * jj;
            if (n < N)
                g_buf0[m * N + n] = __fadd_rn(__fadd_rn(slo, clo), bias[n]);
            if (n + 1 < N)
                g_buf0[m * N + n + 1] = __fadd_rn(__fadd_rn(shi, chi), bias[n + 1]);
        }
    }
}

// ------------------------- GEMM NT packed compensated -----------------------
__global__ void __launch_bounds__(256) gemm_nt_comp_kernel(
    int asel, int csel, const float* __restrict__ B,
    const float* __restrict__ bias, int N, int K) {
    const float* A = bufsel(asel);
    float* C = bufsel(csel);
    __shared__ __align__(16) float As[8][68];
    __shared__ __align__(16) float Bs[8][68];
    int m0 = blockIdx.x * 64, n0 = blockIdx.y * 64;
    int tid = threadIdx.x;
    int tx = tid & 15, ty = tid >> 4;
    ull s2[4][2], c2[4][2];
#pragma unroll
    for (int i = 0; i < 4; i++)
#pragma unroll
        for (int j = 0; j < 2; j++) { s2[i][j] = 0ull; c2[i][j] = 0ull; }

    for (int k0 = 0; k0 < K; k0 += 8) {
#pragma unroll
        for (int l = 0; l < 2; l++) {
            int e = tid + l * 256;
            int m = e >> 3, k = e & 7;
            float v = 0.f;
            if (k0 + k < K) v = A[(m0 + m) * K + (k0 + k)];
            As[k][m] = v;
        }
#pragma unroll
        for (int l = 0; l < 2; l++) {
            int e = tid + l * 256;
            int n = e >> 3, k = e & 7;
            float v = 0.f;
            if ((n0 + n < N) && (k0 + k < K)) v = B[(n0 + n) * K + (k0 + k)];
            Bs[k][n] = v;
        }
        __syncthreads();
#pragma unroll
        for (int k = 0; k < 8; k++) {
            float4 av = *reinterpret_cast<const float4*>(&As[k][ty * 4]);
            const ull* pb = reinterpret_cast<const ull*>(&Bs[k][tx * 4]);
            ull b0 = pb[0], b1 = pb[1];
            ull a0 = pack2(av.x, av.x);
            ull a1 = pack2(av.y, av.y);
            ull a2 = pack2(av.z, av.z);
            ull a3 = pack2(av.w, av.w);
            kacc2x2(a0, b0, s2[0][0], c2[0][0]);
            kacc2x2(a0, b1, s2[0][1], c2[0][1]);
            kacc2x2(a1, b0, s2[1][0], c2[1][0]);
            kacc2x2(a1, b1, s2[1][1], c2[1][1]);
            kacc2x2(a2, b0, s2[2][0], c2[2][0]);
            kacc2x2(a2, b1, s2[2][1], c2[2][1]);
            kacc2x2(a3, b0, s2[3][0], c2[3][0]);
            kacc2x2(a3, b1, s2[3][1], c2[3][1]);
        }
        __syncthreads();
    }
#pragma unroll
    for (int i = 0; i < 4; i++) {
        int m = m0 + ty * 4 + i;
#pragma unroll
        for (int jj = 0; jj < 2; jj++) {
            float slo, shi, clo, chi;
            unpack2(s2[i][jj], slo, shi);
            unpack2(c2[i][jj], clo, chi);
            int n = n0 + tx * 4 + 2 * jj;
            if (n < N)
                C[m * N + n] = __fadd_rn(__fadd_rn(slo, clo), bias[n]);
            if (n + 1 < N)
                C[m * N + n + 1] = __fadd_rn(__fadd_rn(shi, chi), bias[n + 1]);
        }
    }
}

// ------------------------- BN stats: single pass fp64 sum + sumsq -----------
__global__ void bn_stats_kernel() {
    int blk = blockIdx.x;
    int tid = threadIdx.x;
    double ls[4] = {0.0, 0.0, 0.0, 0.0};
    double lq[4] = {0.0, 0.0, 0.0, 0.0};
    int r0 = blk * (MROWS / NSTATB);
    for (int r = r0; r < r0 + (MROWS / NSTATB); r++) {
        const float* row = g_buf0 + r * DIN;
#pragma unroll
        for (int j = 0; j < 4; j++) {
            int c = tid + j * 256;
            if (c < DIN) {
                double v = (double)row[c];
                ls[j] += v;
                lq[j] += v * v;
            }
        }
    }
#pragma unroll
    for (int j = 0; j < 4; j++) {
        int c = tid + j * 256;
        if (c < DIN) {
            g_psumd[blk * DIN + c] = ls[j];
            g_psqd [blk * DIN + c] = lq[j];
        }
    }
}

__global__ void bn_fin_kernel() {
    int c = blockIdx.x * blockDim.x + threadIdx.x;
    if (c >= DIN) return;
    double s = 0.0, q = 0.0;
    for (int i = 0; i < NSTATB; i++) {
        s += g_psumd[i * DIN + c];
        q += g_psqd [i * DIN + c];
    }
    float sumf = (float)s;
    g_mean[c] = __fdiv_rn(sumf, (float)MROWS);
    double meand = s / (double)MROWS;
    double vard = q / (double)MROWS - meand * meand;
    float var = (float)vard;
    g_rs[c] = rsqrtf(__fadd_rn(var, EPS_BN));
}

// ------------------------- fused BN apply + sigmoid + axon1 (in place) ------
__global__ void axon1_bn_kernel(const float* __restrict__ gamma,
                                const float* __restrict__ beta,
                                const float* __restrict__ a1,
                                const float* __restrict__ a2) {
    int idx = blockIdx.x * blockDim.x + threadIdx.x;
    if (idx >= BATCH * DIN) return;
    int b = idx / DIN, c = idx - b * DIN;
    float A1 = a1[c], A2 = a2[c];
    float mean = g_mean[c], rs = g_rs[c], gm = gamma[c], bt = beta[c];
    float p1 = 0.f, p2 = 0.f;
    int off = b * T_STEPS * DIN + c;
    for (int t = 0; t < T_STEPS; t++, off += DIN) {
        float v = __fsub_rn(g_buf0[off], mean);
        v = __fmul_rn(gm, v);
        v = __fmul_rn(v, rs);
        v = __fadd_rn(v, bt);
        float x = sigmoid_exact(v);
        float p = __fadd_rn(__fadd_rn(__fmul_rn(A1, p1), __fmul_rn(A2, p2)), x);
        g_buf0[off] = p;
        p2 = p1;
        p1 = p;
    }
}

// ------------------------- axon (layers 2,3): IIR over T (in place) ---------
__global__ void axon_kernel(int bsel, const float* __restrict__ a1,
                            const float* __restrict__ a2, int C) {
    float* buf = bufsel(bsel);
    int idx = blockIdx.x * blockDim.x + threadIdx.x;
    if (idx >= BATCH * C) return;
    int b = idx / C, c = idx - b * C;
    float A1 = a1[c], A2 = a2[c];
    float p1 = 0.f, p2 = 0.f;
    int off = b * T_STEPS * C + c;
    for (int t = 0; t < T_STEPS; t++, off += C) {
        float x = buf[off];
        float p = __fadd_rn(__fadd_rn(__fmul_rn(A1, p1), __fmul_rn(A2, p2)), x);
        buf[off] = p;
        p2 = p1;
        p1 = p;
    }
}

// ------------------------- LIF scan + dropout mask (mask read [B,H,T]) ------
__global__ void lif_kernel(int bsel, const float* __restrict__ mask) {
    float* buf = bufsel(bsel);
    int idx = blockIdx.x * blockDim.x + threadIdx.x;
    if (idx >= BATCH * HID) return;
    int b = idx / HID, c = idx - b * HID;
    float v = 0.f, s = 0.f;
    int off = b * T_STEPS * HID + c;
    int moff = (b * HID + c) * T_STEPS;
    for (int t = 0; t < T_STEPS; t++, off += HID) {
        float z = buf[off];
        v = __fadd_rn(__fmul_rn(__fmul_rn(DECAY_M, v), __fsub_rn(1.0f, s)), z);
        s = (v > 1.0f) ? 1.0f : 0.0f;
        buf[off] = __fmul_rn(s, mask[moff + t]);
    }
}

// ------------------------- GEMM3 (N=10): compensated ------------------------
__global__ void __launch_bounds__(256) gemm3_kernel(
    const float* __restrict__ W3, const float* __restrict__ b3) {
    __shared__ float sW[NOUT][HID];
    int tid = threadIdx.x;
    for (int i = tid; i < NOUT * HID; i += 256) sW[i / HID][i % HID] = W3[i];
    __syncthreads();
    int idx = blockIdx.x * 256 + tid;
    int r = idx / NOUT, o = idx - r * NOUT;
    const float* a = g_buf2 + r * HID;
    float s = 0.f, c = 0.f;
    for (int k = 0; k < HID; k++) kacc2(a[k], sW[o][k], s, c);
    float acc = __fsub_rn(s, c);
    g_buf3[r * NOUT + o] = __fadd_rn(acc, b3[o]);
}

// ------------------------- final LIF + output transpose [B,10,T] ------------
__global__ void lif3_out_kernel(float* __restrict__ out) {
    int idx = blockIdx.x * blockDim.x + threadIdx.x;
    if (idx >= BATCH * NOUT) return;
    int b = idx / NOUT, o = idx - b * NOUT;
    float v = 0.f, s = 0.f;
    for (int t = 0; t < T_STEPS; t++) {
        float z = g_buf3[(b * T_STEPS + t) * NOUT + o];
        v = __fadd_rn(__fmul_rn(__fmul_rn(DECAY_M, v), __fsub_rn(1.0f, s)), z);
        s = (v > 1.0f) ? 1.0f : 0.0f;
        out[(b * NOUT + o) * T_STEPS + t] = s;
    }
}

// ------------------------- launch -------------------------------------------
extern "C" void kernel_launch(void* const* d_in, const int* in_sizes, int n_in,
                              void* d_out, int out_size) {
    const float* inputs = (const float*)d_in[0];
    const float* W_mlp  = (const float*)d_in[1];
    const float* b_mlp  = (const float*)d_in[2];
    const float* gamma  = (const float*)d_in[3];
    const float* beta   = (const float*)d_in[4];
    const float* a1_1   = (const float*)d_in[5];
    const float* a2_1   = (const float*)d_in[6];
    const float* W1     = (const float*)d_in[7];
    const float* b1     = (const float*)d_in[8];
    const float* a1_2   = (const float*)d_in[9];
    const float* a2_2   = (const float*)d_in[10];
    const float* W2     = (const float*)d_in[11];
    const float* b2     = (const float*)d_in[12];
    const float* a1_3   = (const float*)d_in[13];
    const float* a2_3   = (const float*)d_in[14];
    const float* W3     = (const float*)d_in[15];
    const float* b3     = (const float*)d_in[16];
    const float* mask1  = (const float*)d_in[17];
    const float* mask2  = (const float*)d_in[18];
    float* out = (float*)d_out;

    gemm_mlp_comp_kernel<<<dim3(MROWS / 64, (DIN + 63) / 64), 256>>>(inputs, W_mlp, b_mlp);

    bn_stats_kernel<<<NSTATB, 256>>>();
    bn_fin_kernel<<<(DIN + 255) / 256, 256>>>();

    axon1_bn_kernel<<<(BATCH * DIN + 255) / 256, 256>>>(gamma, beta, a1_1, a2_1);
    gemm_nt_comp_kernel<<<dim3(MROWS / 64, (HID + 63) / 64), 256>>>(0, 1, W1, b1, HID, DIN);
    lif_kernel<<<(BATCH * HID + 255) / 256, 256>>>(1, mask1);

    axon_kernel<<<(BATCH * HID + 255) / 256, 256>>>(1, a1_2, a2_2, HID);
    gemm_nt_comp_kernel<<<dim3(MROWS / 64, (HID + 63) / 64), 256>>>(1, 2, W2, b2, HID, HID);
    lif_kernel<<<(BATCH * HID + 255) / 256, 256>>>(2, mask2);

    axon_kernel<<<(BATCH * HID + 255) / 256, 256>>>(2, a1_3, a2_3, HID);
    gemm3_kernel<<<MROWS * NOUT / 256, 256>>>(W3, b3);
    lif3_out_kernel<<<(BATCH * NOUT + 255) / 256, 256>>>(out);
}